// round 16
// baseline (speedup 1.0000x reference)
#include <cuda_runtime.h>
#include <cuda_fp16.h>

#define D 256
#define H1 128
#define H2 64
#define N_NODES_MAX 100000
#define GRID_BLOCKS 8880

// Folded weights: g_w[0..255] = class-0 column of W1@W2@W3, g_w[256..511] = class 1.
__device__ float g_w[2 * D];
__device__ float g_b[2];
// fp16 copy of h: one row = 256 halves = 512 B = 32 uint4. 51.2 MB scratch.
__device__ uint4 g_h16[N_NODES_MAX * (D / 8)];

// Work-stealing + gate state (self-resetting each launch; graph-replay safe).
__device__ int g_cursor = 0;            // next prologue chunk to steal
__device__ int g_done   = 0;            // completed prologue chunks
__device__ int g_exit   = 0;            // blocks finished (for reset)
__device__ volatile int g_flag = 0;     // prologue complete

// 16-byte-aligned half2x4 <-> uint4 bridge.
union __align__(16) H2x4 {
    __half2 h[4];
    uint4   u;
};

// Per-lane accumulate of one edge in fp16 (HMUL2 + HFMA2), fp32 final sum.
__device__ __forceinline__ void edge_accum_h(const uint4& xv, const uint4& yv,
                                             const __half2* w0h,
                                             const __half2* w1h,
                                             float& out0, float& out1) {
    const __half2* xh = (const __half2*)&xv;
    const __half2* yh = (const __half2*)&yv;
    __half2 a0 = __float2half2_rn(0.0f);
    __half2 a1 = __float2half2_rn(0.0f);
#pragma unroll
    for (int k = 0; k < 4; ++k) {
        const __half2 p = __hmul2(xh[k], yh[k]);
        a0 = __hfma2(p, w0h[k], a0);
        a1 = __hfma2(p, w1h[k], a1);
    }
    const float2 f0 = __half22float2(a0);
    const float2 f1 = __half22float2(a1);
    out0 = f0.x + f0.y;
    out1 = f1.x + f1.y;
}

// ---------------------------------------------------------------------------
// Fused kernel. Phase 1: work-steal prologue chunks (h fp32->fp16 conversion
// + weight fold); resident first wave completes ALL chunks, sets gate flag.
// Phase 2: all blocks pass the gate, then run the 4-edge-per-warp loop.
// Last block out resets the steal/gate state for the next graph replay.
// NOTE: shared float arrays are __align__(16) — they are read via float4,
// and natural float[] alignment (4 B) caused the R14/R15 misaligned traps.
// ---------------------------------------------------------------------------
__global__ void __launch_bounds__(256, 6)
edge_predict_fused(const float* __restrict__ h, int nElems, int convChunks,
                   const float* __restrict__ W1, const float* __restrict__ W2,
                   const float* __restrict__ W3, const float* __restrict__ b1,
                   const float* __restrict__ b2, const float* __restrict__ b3,
                   const int* __restrict__ edges, float* __restrict__ out, int E) {
    const int tid  = threadIdx.x;
    const int warp = tid >> 5;
    const int lane = tid & 31;

    __shared__ __align__(16) float sW23c0[H1];
    __shared__ __align__(16) float sW23c1[H1];
    __shared__ __align__(16) float sTvec[H2];
    __shared__ int sChunk;

    const int totalChunks = convChunks + 32;

    // ---------------- Phase 1: work-stealing prologue ----------------
    for (;;) {
        if (tid == 0) sChunk = atomicAdd(&g_cursor, 1);
        __syncthreads();
        const int c = sChunk;
        __syncthreads();           // protect sChunk before next steal
        if (c >= totalChunks) break;

        if (c < convChunks) {
            // Convert 2048 floats: thread tid handles 8 (two float4 -> uint4).
            const int idx = c * 256 + tid;
            if (idx * 8 < nElems) {
                const float4* src = (const float4*)h + idx * 2;
                const float4 f0 = __ldg(src);
                const float4 f1 = __ldg(src + 1);
                H2x4 hh;
                hh.h[0] = __floats2half2_rn(f0.x, f0.y);
                hh.h[1] = __floats2half2_rn(f0.z, f0.w);
                hh.h[2] = __floats2half2_rn(f1.x, f1.y);
                hh.h[3] = __floats2half2_rn(f1.z, f1.w);
                g_h16[idx] = hh.u;
            }
        } else {
            // Fold chunk fb in [0,32): W23 redundantly in smem, 8 W_eff rows.
            const int fb = c - convChunks;
            {   // W23 entry (k = tid>>1, cls = tid&1): length-64 dot
                const int k   = tid >> 1;
                const int cls = tid & 1;
                const float* w2row = &W2[k * H2];
                float acc = 0.0f;
#pragma unroll 16
                for (int j = 0; j < H2; ++j)
                    acc = fmaf(w2row[j], W3[j * 2 + cls], acc);
                if (cls == 0) sW23c0[k] = acc;
                else          sW23c1[k] = acc;
            }
            __syncthreads();
            {   // W_eff row 8*fb + warp
                const int row = fb * 8 + warp;
                const float4 a  = *(const float4*)&W1[row * H1 + 4 * lane];
                const float4 c0 = *(const float4*)&sW23c0[4 * lane];
                const float4 c1 = *(const float4*)&sW23c1[4 * lane];
                float s0, s1;
                s0 = a.x * c0.x;            s1 = a.x * c1.x;
                s0 = fmaf(a.y, c0.y, s0);   s1 = fmaf(a.y, c1.y, s1);
                s0 = fmaf(a.z, c0.z, s0);   s1 = fmaf(a.z, c1.z, s1);
                s0 = fmaf(a.w, c0.w, s0);   s1 = fmaf(a.w, c1.w, s1);
#pragma unroll
                for (int o = 16; o > 0; o >>= 1) {
                    s0 += __shfl_xor_sync(0xffffffffu, s0, o);
                    s1 += __shfl_xor_sync(0xffffffffu, s1, o);
                }
                if (lane == 0) {
                    g_w[row]     = s0;
                    g_w[D + row] = s1;
                }
            }
            if (fb == 0) {   // bias chain
#pragma unroll
                for (int jj = 0; jj < 8; ++jj) {
                    const int j = warp * 8 + jj;
                    float v =      b1[lane]      * W2[(lane)      * H2 + j];
                    v = fmaf(b1[lane + 32],  W2[(lane + 32) * H2 + j], v);
                    v = fmaf(b1[lane + 64],  W2[(lane + 64) * H2 + j], v);
                    v = fmaf(b1[lane + 96],  W2[(lane + 96) * H2 + j], v);
#pragma unroll
                    for (int o = 16; o > 0; o >>= 1)
                        v += __shfl_xor_sync(0xffffffffu, v, o);
                    if (lane == 0) sTvec[j] = v + b2[j];
                }
                __syncthreads();
                if (warp == 0) {
                    float t0 = sTvec[lane], t1 = sTvec[lane + 32];
                    float bb0 = fmaf(t0, W3[lane * 2 + 0], t1 * W3[(lane + 32) * 2 + 0]);
                    float bb1 = fmaf(t0, W3[lane * 2 + 1], t1 * W3[(lane + 32) * 2 + 1]);
#pragma unroll
                    for (int o = 16; o > 0; o >>= 1) {
                        bb0 += __shfl_xor_sync(0xffffffffu, bb0, o);
                        bb1 += __shfl_xor_sync(0xffffffffu, bb1, o);
                    }
                    if (lane == 0) {
                        g_b[0] = bb0 + b3[0];
                        g_b[1] = bb1 + b3[1];
                    }
                }
            }
            __syncthreads();
        }

        // Publish this chunk's writes, count it; last chunk raises the flag.
        __syncthreads();
        if (tid == 0) {
            __threadfence();
            const int prev = atomicAdd(&g_done, 1);
            if (prev == totalChunks - 1) g_flag = 1;
        }
    }

    // ---------------- Gate: wait until ALL prologue chunks done ----------------
    if (tid == 0) {
        while (g_flag == 0) __nanosleep(64);
    }
    __syncthreads();
    __threadfence();

    // ---------------- Phase 2: edge loop (R13-proven) ----------------
    const int  gwarp  = (blockIdx.x * blockDim.x + tid) >> 5;
    const int  nwarps = (gridDim.x * blockDim.x) >> 5;
    const int  nQuads = E >> 2;
    const char* tbl   = (const char*)g_h16;
    const unsigned laneOff = (unsigned)lane << 4;

    __half2 w0h[4], w1h[4];
#pragma unroll
    for (int k = 0; k < 4; ++k) {
        w0h[k] = __floats2half2_rn(g_w[8 * lane + 2 * k],     g_w[8 * lane + 2 * k + 1]);
        w1h[k] = __floats2half2_rn(g_w[D + 8 * lane + 2 * k], g_w[D + 8 * lane + 2 * k + 1]);
    }
    const float bias0 = g_b[0];
    const float bias1 = g_b[1];
    const bool hi16 = (lane & 16) != 0;
    const bool hi8  = (lane & 8)  != 0;
    const bool hi4  = (lane & 4)  != 0;

    for (int p = gwarp; p < nQuads; p += nwarps) {
        const int4 qa = __ldg((const int4*)edges + 2 * p);
        const int4 qb = __ldg((const int4*)edges + 2 * p + 1);

        const uint4 x0 = __ldg((const uint4*)(tbl + (((unsigned)qa.x << 9) + laneOff)));
        const uint4 y0 = __ldg((const uint4*)(tbl + (((unsigned)qa.y << 9) + laneOff)));
        const uint4 x1 = __ldg((const uint4*)(tbl + (((unsigned)qa.z << 9) + laneOff)));
        const uint4 y1 = __ldg((const uint4*)(tbl + (((unsigned)qa.w << 9) + laneOff)));
        const uint4 x2 = __ldg((const uint4*)(tbl + (((unsigned)qb.x << 9) + laneOff)));
        const uint4 y2 = __ldg((const uint4*)(tbl + (((unsigned)qb.y << 9) + laneOff)));
        const uint4 x3 = __ldg((const uint4*)(tbl + (((unsigned)qb.z << 9) + laneOff)));
        const uint4 y3 = __ldg((const uint4*)(tbl + (((unsigned)qb.w << 9) + laneOff)));

        float L00, L01, L10, L11, L20, L21, L30, L31;
        edge_accum_h(x0, y0, w0h, w1h, L00, L01);
        edge_accum_h(x1, y1, w0h, w1h, L10, L11);
        edge_accum_h(x2, y2, w0h, w1h, L20, L21);
        edge_accum_h(x3, y3, w0h, w1h, L30, L31);

        float v0 = (hi16 ? L20 : L00) + __shfl_xor_sync(0xffffffffu, hi16 ? L00 : L20, 16);
        float v1 = (hi16 ? L21 : L01) + __shfl_xor_sync(0xffffffffu, hi16 ? L01 : L21, 16);
        float v2 = (hi16 ? L30 : L10) + __shfl_xor_sync(0xffffffffu, hi16 ? L10 : L30, 16);
        float v3 = (hi16 ? L31 : L11) + __shfl_xor_sync(0xffffffffu, hi16 ? L11 : L31, 16);
        float w0 = (hi8 ? v2 : v0) + __shfl_xor_sync(0xffffffffu, hi8 ? v0 : v2, 8);
        float w1 = (hi8 ? v3 : v1) + __shfl_xor_sync(0xffffffffu, hi8 ? v1 : v3, 8);
        float u  = (hi4 ? w1 : w0) + __shfl_xor_sync(0xffffffffu, hi4 ? w0 : w1, 4);
        u += __shfl_xor_sync(0xffffffffu, u, 2);
        u += __shfl_xor_sync(0xffffffffu, u, 1);
        const float uo = __shfl_xor_sync(0xffffffffu, u, 4);

        if ((lane & 7) == 0) {
            const float l0 = u  + bias0;
            const float l1 = uo + bias1;
            const float m  = fmaxf(l0, l1);
            const float e0 = expf(l0 - m);
            const float e1 = expf(l1 - m);
            const float inv = 1.0f / (e0 + e1);
            ((float2*)out)[4 * p + (lane >> 3)] = make_float2(e0 * inv, e1 * inv);
        }
    }

    // Tail for E not divisible by 4 (not hit for E = 1M).
    if (blockIdx.x == 0 && warp == 0) {
        for (int e = nQuads * 4; e < E; ++e) {
            const int2 st = __ldg((const int2*)edges + e);
            const uint4 xv = __ldg((const uint4*)(tbl + (((unsigned)st.x << 9) + laneOff)));
            const uint4 yv = __ldg((const uint4*)(tbl + (((unsigned)st.y << 9) + laneOff)));
            float a0, a1;
            edge_accum_h(xv, yv, w0h, w1h, a0, a1);
#pragma unroll
            for (int o = 16; o > 0; o >>= 1) {
                a0 += __shfl_xor_sync(0xffffffffu, a0, o);
                a1 += __shfl_xor_sync(0xffffffffu, a1, o);
            }
            if (lane == 0) {
                a0 += bias0; a1 += bias1;
                const float m  = fmaxf(a0, a1);
                const float e0 = expf(a0 - m);
                const float e1 = expf(a1 - m);
                const float inv = 1.0f / (e0 + e1);
                ((float2*)out)[e] = make_float2(e0 * inv, e1 * inv);
            }
        }
    }

    // ---------------- Reset state for the next graph replay ----------------
    __syncthreads();
    if (tid == 0) {
        const int prev = atomicAdd(&g_exit, 1);
        if (prev == (int)gridDim.x - 1) {
            g_cursor = 0;
            g_done   = 0;
            g_flag   = 0;
            __threadfence();
            g_exit   = 0;
        }
    }
}

extern "C" void kernel_launch(void* const* d_in, const int* in_sizes, int n_in,
                              void* d_out, int out_size) {
    const float* h     = (const float*)d_in[0];
    const int*   edges = (const int*)d_in[1];
    const float* W1    = (const float*)d_in[2];
    const float* b1    = (const float*)d_in[3];
    const float* W2    = (const float*)d_in[4];
    const float* b2    = (const float*)d_in[5];
    const float* W3    = (const float*)d_in[6];
    const float* b3    = (const float*)d_in[7];
    float*       out   = (float*)d_out;

    const int nElems = in_sizes[0];
    const int E      = in_sizes[1] / 2;
    const int convChunks = (nElems / 8 + 255) / 256;   // 12500

    edge_predict_fused<<<GRID_BLOCKS, 256>>>(h, nElems, convChunks,
                                             W1, W2, W3, b1, b2, b3,
                                             edges, out, E);
}

// round 17
// speedup vs baseline: 1.1240x; 1.1240x over previous
#include <cuda_runtime.h>
#include <cuda_fp16.h>

#define D 256
#define H1 128
#define H2 64
#define N_NODES_MAX 100000
#define GRID_BLOCKS 8880
#define CONV_BLOCKS 888   // = 148 SMs x 6 CTAs: exactly the first wave

// Folded weights: g_w[0..255] = class-0 column of W1@W2@W3, g_w[256..511] = class 1.
__device__ float g_w[2 * D];
__device__ float g_b[2];
// fp16 copy of h: one row = 256 halves = 512 B = 32 uint4. 51.2 MB scratch.
__device__ uint4 g_h16[N_NODES_MAX * (D / 8)];

// Gate state (self-resetting each launch; graph-replay safe).
__device__ int g_done = 0;              // converter blocks finished
__device__ int g_exit = 0;              // blocks finished (for reset)
__device__ volatile int g_flag = 0;     // prologue complete

// 16-byte-aligned half2x4 <-> uint4 bridge.
union __align__(16) H2x4 {
    __half2 h[4];
    uint4   u;
};

// Per-lane accumulate of one edge in fp16 (HMUL2 + HFMA2), fp32 final sum.
__device__ __forceinline__ void edge_accum_h(const uint4& xv, const uint4& yv,
                                             const __half2* w0h,
                                             const __half2* w1h,
                                             float& out0, float& out1) {
    const __half2* xh = (const __half2*)&xv;
    const __half2* yh = (const __half2*)&yv;
    __half2 a0 = __float2half2_rn(0.0f);
    __half2 a1 = __float2half2_rn(0.0f);
#pragma unroll
    for (int k = 0; k < 4; ++k) {
        const __half2 p = __hmul2(xh[k], yh[k]);
        a0 = __hfma2(p, w0h[k], a0);
        a1 = __hfma2(p, w1h[k], a1);
    }
    const float2 f0 = __half22float2(a0);
    const float2 f1 = __half22float2(a1);
    out0 = f0.x + f0.y;
    out1 = f1.x + f1.y;
}

// ---------------------------------------------------------------------------
// Fused kernel, static-partition prologue:
//   blocks 0..CONV_BLOCKS-1: barrier-free grid-stride fp32->fp16 conversion
//   blocks 0..31           : also the weight fold (proven R13 code)
//   all blocks             : gate on flag, then the R13 edge loop
// Last block out resets gate state for the next graph replay.
// ---------------------------------------------------------------------------
__global__ void __launch_bounds__(256, 6)
edge_predict_fused(const float* __restrict__ h, int nElems,
                   const float* __restrict__ W1, const float* __restrict__ W2,
                   const float* __restrict__ W3, const float* __restrict__ b1,
                   const float* __restrict__ b2, const float* __restrict__ b3,
                   const int* __restrict__ edges, float* __restrict__ out, int E) {
    const int tid  = threadIdx.x;
    const int warp = tid >> 5;
    const int lane = tid & 31;

    __shared__ __align__(16) float sW23c0[H1];
    __shared__ __align__(16) float sW23c1[H1];
    __shared__ __align__(16) float sTvec[H2];

    // ---------------- Prologue (converter blocks only) ----------------
    if (blockIdx.x < CONV_BLOCKS) {
        // Fold: blocks 0..31, 8 W_eff rows each (W23 redundant in smem).
        if (blockIdx.x < 32) {
            const int fb = blockIdx.x;
            {   // W23 entry (k = tid>>1, cls = tid&1): length-64 dot
                const int k   = tid >> 1;
                const int cls = tid & 1;
                const float* w2row = &W2[k * H2];
                float acc = 0.0f;
#pragma unroll 16
                for (int j = 0; j < H2; ++j)
                    acc = fmaf(w2row[j], W3[j * 2 + cls], acc);
                if (cls == 0) sW23c0[k] = acc;
                else          sW23c1[k] = acc;
            }
            __syncthreads();
            {   // W_eff row 8*fb + warp
                const int row = fb * 8 + warp;
                const float4 a  = *(const float4*)&W1[row * H1 + 4 * lane];
                const float4 c0 = *(const float4*)&sW23c0[4 * lane];
                const float4 c1 = *(const float4*)&sW23c1[4 * lane];
                float s0, s1;
                s0 = a.x * c0.x;            s1 = a.x * c1.x;
                s0 = fmaf(a.y, c0.y, s0);   s1 = fmaf(a.y, c1.y, s1);
                s0 = fmaf(a.z, c0.z, s0);   s1 = fmaf(a.z, c1.z, s1);
                s0 = fmaf(a.w, c0.w, s0);   s1 = fmaf(a.w, c1.w, s1);
#pragma unroll
                for (int o = 16; o > 0; o >>= 1) {
                    s0 += __shfl_xor_sync(0xffffffffu, s0, o);
                    s1 += __shfl_xor_sync(0xffffffffu, s1, o);
                }
                if (lane == 0) {
                    g_w[row]     = s0;
                    g_w[D + row] = s1;
                }
            }
            if (fb == 0) {   // bias chain
#pragma unroll
                for (int jj = 0; jj < 8; ++jj) {
                    const int j = warp * 8 + jj;
                    float v =      b1[lane]      * W2[(lane)      * H2 + j];
                    v = fmaf(b1[lane + 32],  W2[(lane + 32) * H2 + j], v);
                    v = fmaf(b1[lane + 64],  W2[(lane + 64) * H2 + j], v);
                    v = fmaf(b1[lane + 96],  W2[(lane + 96) * H2 + j], v);
#pragma unroll
                    for (int o = 16; o > 0; o >>= 1)
                        v += __shfl_xor_sync(0xffffffffu, v, o);
                    if (lane == 0) sTvec[j] = v + b2[j];
                }
                __syncthreads();
                if (warp == 0) {
                    float t0 = sTvec[lane], t1 = sTvec[lane + 32];
                    float bb0 = fmaf(t0, W3[lane * 2 + 0], t1 * W3[(lane + 32) * 2 + 0]);
                    float bb1 = fmaf(t0, W3[lane * 2 + 1], t1 * W3[(lane + 32) * 2 + 1]);
#pragma unroll
                    for (int o = 16; o > 0; o >>= 1) {
                        bb0 += __shfl_xor_sync(0xffffffffu, bb0, o);
                        bb1 += __shfl_xor_sync(0xffffffffu, bb1, o);
                    }
                    if (lane == 0) {
                        g_b[0] = bb0 + b3[0];
                        g_b[1] = bb1 + b3[1];
                    }
                }
            }
        }

        // Conversion: barrier-free grid-stride over uint4 slots (full MLP).
        const int nU = nElems >> 3;                   // 3.2M uint4 slots
        for (int idx = blockIdx.x * 256 + tid; idx < nU; idx += CONV_BLOCKS * 256) {
            const float4* src = (const float4*)h + idx * 2;
            const float4 f0 = __ldg(src);
            const float4 f1 = __ldg(src + 1);
            H2x4 hh;
            hh.h[0] = __floats2half2_rn(f0.x, f0.y);
            hh.h[1] = __floats2half2_rn(f0.z, f0.w);
            hh.h[2] = __floats2half2_rn(f1.x, f1.y);
            hh.h[3] = __floats2half2_rn(f1.z, f1.w);
            g_h16[idx] = hh.u;
        }

        __syncthreads();
        if (tid == 0) {
            __threadfence();
            if (atomicAdd(&g_done, 1) == CONV_BLOCKS - 1) g_flag = 1;
        }
    }

    // ---------------- Gate ----------------
    if (tid == 0) {
        while (g_flag == 0) __nanosleep(128);
    }
    __syncthreads();
    __threadfence();

    // ---------------- Edge loop (R13-proven) ----------------
    const int  gwarp  = (blockIdx.x * blockDim.x + tid) >> 5;
    const int  nwarps = (gridDim.x * blockDim.x) >> 5;
    const int  nQuads = E >> 2;
    const char* tbl   = (const char*)g_h16;
    const unsigned laneOff = (unsigned)lane << 4;

    __half2 w0h[4], w1h[4];
#pragma unroll
    for (int k = 0; k < 4; ++k) {
        w0h[k] = __floats2half2_rn(g_w[8 * lane + 2 * k],     g_w[8 * lane + 2 * k + 1]);
        w1h[k] = __floats2half2_rn(g_w[D + 8 * lane + 2 * k], g_w[D + 8 * lane + 2 * k + 1]);
    }
    const float bias0 = g_b[0];
    const float bias1 = g_b[1];
    const bool hi16 = (lane & 16) != 0;
    const bool hi8  = (lane & 8)  != 0;
    const bool hi4  = (lane & 4)  != 0;

    for (int p = gwarp; p < nQuads; p += nwarps) {
        const int4 qa = __ldg((const int4*)edges + 2 * p);
        const int4 qb = __ldg((const int4*)edges + 2 * p + 1);

        const uint4 x0 = __ldg((const uint4*)(tbl + (((unsigned)qa.x << 9) + laneOff)));
        const uint4 y0 = __ldg((const uint4*)(tbl + (((unsigned)qa.y << 9) + laneOff)));
        const uint4 x1 = __ldg((const uint4*)(tbl + (((unsigned)qa.z << 9) + laneOff)));
        const uint4 y1 = __ldg((const uint4*)(tbl + (((unsigned)qa.w << 9) + laneOff)));
        const uint4 x2 = __ldg((const uint4*)(tbl + (((unsigned)qb.x << 9) + laneOff)));
        const uint4 y2 = __ldg((const uint4*)(tbl + (((unsigned)qb.y << 9) + laneOff)));
        const uint4 x3 = __ldg((const uint4*)(tbl + (((unsigned)qb.z << 9) + laneOff)));
        const uint4 y3 = __ldg((const uint4*)(tbl + (((unsigned)qb.w << 9) + laneOff)));

        float L00, L01, L10, L11, L20, L21, L30, L31;
        edge_accum_h(x0, y0, w0h, w1h, L00, L01);
        edge_accum_h(x1, y1, w0h, w1h, L10, L11);
        edge_accum_h(x2, y2, w0h, w1h, L20, L21);
        edge_accum_h(x3, y3, w0h, w1h, L30, L31);

        float v0 = (hi16 ? L20 : L00) + __shfl_xor_sync(0xffffffffu, hi16 ? L00 : L20, 16);
        float v1 = (hi16 ? L21 : L01) + __shfl_xor_sync(0xffffffffu, hi16 ? L01 : L21, 16);
        float v2 = (hi16 ? L30 : L10) + __shfl_xor_sync(0xffffffffu, hi16 ? L10 : L30, 16);
        float v3 = (hi16 ? L31 : L11) + __shfl_xor_sync(0xffffffffu, hi16 ? L11 : L31, 16);
        float w0 = (hi8 ? v2 : v0) + __shfl_xor_sync(0xffffffffu, hi8 ? v0 : v2, 8);
        float w1 = (hi8 ? v3 : v1) + __shfl_xor_sync(0xffffffffu, hi8 ? v1 : v3, 8);
        float u  = (hi4 ? w1 : w0) + __shfl_xor_sync(0xffffffffu, hi4 ? w0 : w1, 4);
        u += __shfl_xor_sync(0xffffffffu, u, 2);
        u += __shfl_xor_sync(0xffffffffu, u, 1);
        const float uo = __shfl_xor_sync(0xffffffffu, u, 4);

        if ((lane & 7) == 0) {
            const float l0 = u  + bias0;
            const float l1 = uo + bias1;
            const float m  = fmaxf(l0, l1);
            const float e0 = expf(l0 - m);
            const float e1 = expf(l1 - m);
            const float inv = 1.0f / (e0 + e1);
            ((float2*)out)[4 * p + (lane >> 3)] = make_float2(e0 * inv, e1 * inv);
        }
    }

    // Tail for E not divisible by 4 (not hit for E = 1M).
    if (blockIdx.x == 0 && warp == 0) {
        for (int e = nQuads * 4; e < E; ++e) {
            const int2 st = __ldg((const int2*)edges + e);
            const uint4 xv = __ldg((const uint4*)(tbl + (((unsigned)st.x << 9) + laneOff)));
            const uint4 yv = __ldg((const uint4*)(tbl + (((unsigned)st.y << 9) + laneOff)));
            float a0, a1;
            edge_accum_h(xv, yv, w0h, w1h, a0, a1);
#pragma unroll
            for (int o = 16; o > 0; o >>= 1) {
                a0 += __shfl_xor_sync(0xffffffffu, a0, o);
                a1 += __shfl_xor_sync(0xffffffffu, a1, o);
            }
            if (lane == 0) {
                a0 += bias0; a1 += bias1;
                const float m  = fmaxf(a0, a1);
                const float e0 = expf(a0 - m);
                const float e1 = expf(a1 - m);
                const float inv = 1.0f / (e0 + e1);
                ((float2*)out)[e] = make_float2(e0 * inv, e1 * inv);
            }
        }
    }

    // ---------------- Reset state for the next graph replay ----------------
    __syncthreads();
    if (tid == 0) {
        const int prev = atomicAdd(&g_exit, 1);
        if (prev == (int)gridDim.x - 1) {
            g_done = 0;
            g_flag = 0;
            __threadfence();
            g_exit = 0;
        }
    }
}

extern "C" void kernel_launch(void* const* d_in, const int* in_sizes, int n_in,
                              void* d_out, int out_size) {
    const float* h     = (const float*)d_in[0];
    const int*   edges = (const int*)d_in[1];
    const float* W1    = (const float*)d_in[2];
    const float* b1    = (const float*)d_in[3];
    const float* W2    = (const float*)d_in[4];
    const float* b2    = (const float*)d_in[5];
    const float* W3    = (const float*)d_in[6];
    const float* b3    = (const float*)d_in[7];
    float*       out   = (float*)d_out;

    const int nElems = in_sizes[0];
    const int E      = in_sizes[1] / 2;

    edge_predict_fused<<<GRID_BLOCKS, 256>>>(h, nElems,
                                             W1, W2, W3, b1, b2, b3,
                                             edges, out, E);
}